// round 2
// baseline (speedup 1.0000x reference)
#include <cuda_runtime.h>
#include <math.h>

#define BB 32
#define HH 512
#define VOCAB 50257
#define VPAD 50432   // 50257 padded up to multiple of 128 (and of 4 for float4)

// ---------------- device scratch (static, no runtime allocation) ----------------
__device__ float g_xcur[BB * HH];          // current input embedding per batch row
__device__ float g_h0[2][BB * HH];         // layer-0 hidden state, double buffered
__device__ float g_h1[2][BB * HH];         // layer-1 hidden state, double buffered
__device__ float g_logits0[BB * HH];       // layer-0 head logits
__device__ float g_x1[BB * HH];            // tanh(softmax(logits0))
__device__ float g_V1p[512 * VPAD];        // V1 repacked with padded row stride (float4-aligned)
__device__ float g_c1p[VPAD];              // c1 padded
__device__ float g_logits1[BB * VPAD];     // big-head logits scratch

// ---------------- init: x_cur = emb[x], states = h_prev ----------------
__global__ void k_init(const int* __restrict__ x, const float* __restrict__ h_prev,
                       const float* __restrict__ emb) {
    int b = blockIdx.x, j = threadIdx.x;
    g_xcur[b * HH + j] = emb[(long)x[b] * HH + j];
    g_h0[0][b * HH + j] = h_prev[b * HH + j];
    g_h1[0][b * HH + j] = h_prev[b * HH + j];
}

// ---------------- repack V1 (and c1) into padded, aligned buffers ----------------
__global__ void k_pack(const float* __restrict__ V1, const float* __restrict__ c1) {
    int k = blockIdx.x;  // 0..511
    for (int c = threadIdx.x; c < VPAD; c += blockDim.x) {
        g_V1p[(long)k * VPAD + c] = (c < VOCAB) ? V1[(long)k * VOCAB + c] : 0.0f;
        if (k == 0) g_c1p[c] = (c < VOCAB) ? c1[c] : 0.0f;
    }
}

// ---------------- small GEMM: out[32,512] = (tanh?)(A@WA (+ Bm@WB) + bias) ----------------
// grid: 16 blocks (32 cols each), 256 threads. Tiled 32x32, K=512 per matrix pair.
__global__ void k_small_gemm(const float* __restrict__ A, const float* __restrict__ WA,
                             const float* __restrict__ Bm, const float* __restrict__ WB,
                             const float* __restrict__ bias, float* __restrict__ out,
                             int applyTanh, float* __restrict__ out_h, int t, int T) {
    __shared__ float As[32][33];
    __shared__ float Ws[32][33];
    int tid = threadIdx.x;
    int tx = tid & 31;   // col within tile
    int ty = tid >> 5;   // 0..7  -> rows ty, ty+8, ty+16, ty+24
    int c0 = blockIdx.x * 32;
    float acc[4] = {0.f, 0.f, 0.f, 0.f};

    for (int pass = 0; pass < 2; pass++) {
        const float* Ap = pass ? Bm : A;
        const float* Wp = pass ? WB : WA;
        if (Ap == nullptr) continue;
        for (int k0 = 0; k0 < 512; k0 += 32) {
            #pragma unroll
            for (int i = 0; i < 4; i++) {
                int lin = tid + i * 256;
                int r = lin >> 5, kk = lin & 31;
                As[r][kk] = Ap[r * 512 + k0 + kk];
                Ws[r][kk] = Wp[(k0 + r) * 512 + c0 + kk];  // Ws[kk_row][col]
            }
            __syncthreads();
            #pragma unroll
            for (int kk = 0; kk < 32; kk++) {
                float w = Ws[kk][tx];
                #pragma unroll
                for (int i = 0; i < 4; i++)
                    acc[i] += As[ty + i * 8][kk] * w;
            }
            __syncthreads();
        }
    }
    #pragma unroll
    for (int i = 0; i < 4; i++) {
        int r = ty + i * 8;
        float v = acc[i] + bias[c0 + tx];
        if (applyTanh) v = tanhf(v);
        out[r * 512 + c0 + tx] = v;
        if (out_h) out_h[((long)r * T + t) * 512 + c0 + tx] = v;
    }
}

// ---------------- layer-0 softmax + tanh: x1 = tanh(softmax(logits0)) ----------------
__global__ void k_softmax_tanh(const float* __restrict__ logits, float* __restrict__ x1) {
    int b = blockIdx.x, j = threadIdx.x;  // 512 threads
    __shared__ float red[512];
    float l = logits[b * 512 + j];
    red[j] = l; __syncthreads();
    for (int s = 256; s > 0; s >>= 1) {
        if (j < s) red[j] = fmaxf(red[j], red[j + s]);
        __syncthreads();
    }
    float M = red[0]; __syncthreads();
    float e = expf(l - M);
    red[j] = e; __syncthreads();
    for (int s = 256; s > 0; s >>= 1) {
        if (j < s) red[j] += red[j + s];
        __syncthreads();
    }
    float S = red[0];
    x1[b * 512 + j] = tanhf(e / S);
}

// ---------------- big GEMM: g_logits1[32, VPAD] = A[32,512] @ g_V1p + g_c1p ----------------
// grid: VPAD/128 = 394 blocks, 256 threads. Each thread: 4 rows x 4 cols (float4).
__global__ void k_big_gemm(const float* __restrict__ A) {
    __shared__ float Ash[32][128];
    int tid = threadIdx.x;
    int lane = tid & 31;
    int wg = tid >> 5;  // 0..7 -> rows wg*4 .. wg*4+3
    int cbase = blockIdx.x * 128 + lane * 4;
    float acc[4][4];
    #pragma unroll
    for (int i = 0; i < 4; i++)
        #pragma unroll
        for (int j = 0; j < 4; j++) acc[i][j] = 0.f;

    for (int k0 = 0; k0 < 512; k0 += 128) {
        #pragma unroll
        for (int i = 0; i < 16; i++) {
            int lin = tid + i * 256;
            int r = lin >> 7, kk = lin & 127;
            Ash[r][kk] = A[r * 512 + k0 + kk];
        }
        __syncthreads();
        #pragma unroll 4
        for (int kk = 0; kk < 128; kk++) {
            float4 bv = *reinterpret_cast<const float4*>(&g_V1p[(long)(k0 + kk) * VPAD + cbase]);
            #pragma unroll
            for (int i = 0; i < 4; i++) {
                float a = Ash[wg * 4 + i][kk];
                acc[i][0] += a * bv.x;
                acc[i][1] += a * bv.y;
                acc[i][2] += a * bv.z;
                acc[i][3] += a * bv.w;
            }
        }
        __syncthreads();
    }
    float4 bias = *reinterpret_cast<const float4*>(&g_c1p[cbase]);
    #pragma unroll
    for (int i = 0; i < 4; i++) {
        int r = wg * 4 + i;
        float4 o;
        o.x = acc[i][0] + bias.x;
        o.y = acc[i][1] + bias.y;
        o.z = acc[i][2] + bias.z;
        o.w = acc[i][3] + bias.w;
        *reinterpret_cast<float4*>(&g_logits1[(long)r * VPAD + cbase]) = o;
    }
}

// ---------------- vocab softmax + argmax + y write + feedback embed ----------------
// grid: 32 blocks (one per batch row), 1024 threads.
__global__ void k_softmax_big(const float* __restrict__ emb, float* __restrict__ out_y,
                              int t, int T) {
    int b = blockIdx.x;
    int tid = threadIdx.x;
    const float* row = &g_logits1[(long)b * VPAD];
    __shared__ float sval[1024];
    __shared__ int sidx[1024];

    // pass 1: max + argmax (first-index tie break, matches jnp.argmax)
    float bm = -1e30f; int bi = 0;
    for (int j = tid; j < VOCAB; j += 1024) {
        float v = row[j];
        if (v > bm) { bm = v; bi = j; }
    }
    sval[tid] = bm; sidx[tid] = bi; __syncthreads();
    for (int s = 512; s > 0; s >>= 1) {
        if (tid < s) {
            float v2 = sval[tid + s]; int i2 = sidx[tid + s];
            if (v2 > sval[tid] || (v2 == sval[tid] && i2 < sidx[tid])) {
                sval[tid] = v2; sidx[tid] = i2;
            }
        }
        __syncthreads();
    }
    float M = sval[0]; int amax = sidx[0];
    __syncthreads();

    // pass 2: sum of exp
    float s = 0.f;
    for (int j = tid; j < VOCAB; j += 1024) s += expf(row[j] - M);
    sval[tid] = s; __syncthreads();
    for (int st = 512; st > 0; st >>= 1) {
        if (tid < st) sval[tid] += sval[tid + st];
        __syncthreads();
    }
    float inv = 1.f / sval[0];

    // pass 3: write normalized y
    float* yrow = &out_y[((long)b * T + t) * VOCAB];
    for (int j = tid; j < VOCAB; j += 1024) yrow[j] = expf(row[j] - M) * inv;

    // greedy feedback: x_cur = embedding[argmax]
    if (tid < 512) g_xcur[b * 512 + tid] = emb[(long)amax * 512 + tid];
}

// ---------------- host launcher ----------------
extern "C" void kernel_launch(void* const* d_in, const int* in_sizes, int n_in,
                              void* d_out, int out_size) {
    const int*   x      = (const int*)d_in[0];
    // d_in[1] = max_len (derived from out_size instead), d_in[2] = eos (unused by reference)
    const float* h_prev = (const float*)d_in[3];
    const float* emb    = (const float*)d_in[4];
    const float* U0     = (const float*)d_in[5];
    const float* W0     = (const float*)d_in[6];
    const float* b0     = (const float*)d_in[7];
    const float* V0     = (const float*)d_in[8];
    const float* c0     = (const float*)d_in[9];
    const float* U1     = (const float*)d_in[10];
    const float* W1     = (const float*)d_in[11];
    const float* b1     = (const float*)d_in[12];
    const float* V1     = (const float*)d_in[13];
    const float* c1     = (const float*)d_in[14];

    float* out = (float*)d_out;
    int T = out_size / (BB * (HH + VOCAB));  // = 64 for this shape
    float* out_h = out;
    float* out_y = out + (long)BB * T * HH;

    // resolve addresses of __device__ buffers
    float *p_xcur, *p_h0, *p_h1, *p_l0, *p_x1;
    cudaGetSymbolAddress((void**)&p_xcur, g_xcur);
    cudaGetSymbolAddress((void**)&p_h0,   g_h0);
    cudaGetSymbolAddress((void**)&p_h1,   g_h1);
    cudaGetSymbolAddress((void**)&p_l0,   g_logits0);
    cudaGetSymbolAddress((void**)&p_x1,   g_x1);

    k_init<<<BB, 512>>>(x, h_prev, emb);
    k_pack<<<512, 256>>>(V1, c1);

    for (int t = 0; t < T; t++) {
        float* h0_in  = p_h0 + (t & 1) * BB * HH;
        float* h0_out = p_h0 + ((t + 1) & 1) * BB * HH;
        float* h1_in  = p_h1 + (t & 1) * BB * HH;
        float* h1_out = p_h1 + ((t + 1) & 1) * BB * HH;

        // layer 0 cell: h0 = tanh(x_cur@U0 + h0_in@W0 + b0)
        k_small_gemm<<<16, 256>>>(p_xcur, U0, h0_in, W0, b0, h0_out, 1, nullptr, 0, T);
        // layer 0 head: logits0 = h0@V0 + c0
        k_small_gemm<<<16, 256>>>(h0_out, V0, nullptr, nullptr, c0, p_l0, 0, nullptr, 0, T);
        // x1 = tanh(softmax(logits0))
        k_softmax_tanh<<<BB, 512>>>(p_l0, p_x1);
        // layer 1 cell: h1 = tanh(x1@U1 + h1_in@W1 + b1); also writes out_h[:,t,:]
        k_small_gemm<<<16, 256>>>(p_x1, U1, h1_in, W1, b1, h1_out, 1, out_h, t, T);
        // big head GEMM: logits1 = h1@V1 + c1
        k_big_gemm<<<VPAD / 128, 256>>>(h1_out);
        // softmax over vocab, write y, argmax feedback into x_cur
        k_softmax_big<<<BB, 1024>>>(emb, out_y, t, T);
    }
}

// round 3
// speedup vs baseline: 2.2392x; 2.2392x over previous
#include <cuda_runtime.h>
#include <cuda_bf16.h>
#include <math.h>
#include <stdint.h>

#define BB 32
#define HH 512
#define VOCAB 50257
#define VPAD  50432          // multiple of 128
#define NB8   (VPAD/8)       // 6304 fragment columns
#define NBLK  (VPAD/128)     // 394 big-gemm blocks
#define NBP   400            // padded partial stride

// ---------------- device scratch ----------------
__device__ float g_xcur[BB * HH];
__device__ float g_h0s[BB * HH];
__device__ float g_h1s[BB * HH];
__device__ uint4 g_Af[2 * 32 * 2 * 32];        // [hl][ks][m][lane] -> 4x b32 A-fragment
__device__ uint4 g_Bf[32 * NB8 * 32];          // [ks][n8][lane] -> {bh0,bh1,bl0,bl1}  (103MB)
__device__ float g_c1p[VPAD];
__device__ float g_E[BB * VPAD];               // exp(logits)
__device__ float g_psum[BB * NBP];
__device__ float g_pmax[BB * NBP];
__device__ int   g_pidx[BB * NBP];
__device__ float g_invS[BB];

// ---------------- helpers ----------------
__device__ __forceinline__ uint32_t pk_bf2(float a, float b) {
    uint32_t ua = (uint32_t)__bfloat16_as_ushort(__float2bfloat16_rn(a));
    uint32_t ub = (uint32_t)__bfloat16_as_ushort(__float2bfloat16_rn(b));
    return ua | (ub << 16);
}
__device__ __forceinline__ float bf_hi(float v) {
    return __bfloat162float(__float2bfloat16_rn(v));
}
__device__ __forceinline__ void mma_bf16(float* d, const uint4& a, uint32_t b0, uint32_t b1) {
    asm volatile(
        "mma.sync.aligned.m16n8k16.row.col.f32.bf16.bf16.f32 "
        "{%0,%1,%2,%3},{%4,%5,%6,%7},{%8,%9},{%0,%1,%2,%3};\n"
        : "+f"(d[0]), "+f"(d[1]), "+f"(d[2]), "+f"(d[3])
        : "r"(a.x), "r"(a.y), "r"(a.z), "r"(a.w), "r"(b0), "r"(b1));
}

// ---------------- init ----------------
__global__ void k_init(const int* __restrict__ x, const float* __restrict__ h_prev,
                       const float* __restrict__ emb) {
    int b = blockIdx.x, j = threadIdx.x;
    g_xcur[b * HH + j] = emb[(long)x[b] * HH + j];
    g_h0s[b * HH + j]  = h_prev[b * HH + j];
    g_h1s[b * HH + j]  = h_prev[b * HH + j];
}

__global__ void k_pack_c1(const float* __restrict__ c1) {
    int i = blockIdx.x * blockDim.x + threadIdx.x;
    if (i < VPAD) g_c1p[i] = (i < VOCAB) ? c1[i] : -1e30f;
}

// ---------------- pack V1 into bf16 split mma-fragment layout ----------------
// grid (197, 32): bx = 256-col chunk, by = ks (16-k tile). 256 threads.
__global__ void k_pack_b(const float* __restrict__ V1) {
    __shared__ float sv[16][257];
    int bx = blockIdx.x, ks = blockIdx.y, tid = threadIdx.x;
    int cbase = bx * 256;
    #pragma unroll
    for (int r = 0; r < 16; r++) {
        int col = cbase + tid;
        int k = ks * 16 + r;
        sv[r][tid] = (col < VOCAB) ? V1[(long)k * VOCAB + col] : 0.0f;
    }
    __syncthreads();
    for (int e = tid; e < 1024; e += 256) {
        int lane = e & 31, n8l = e >> 5;
        int colL = n8l * 8 + (lane >> 2);
        int rr = (lane & 3) * 2;
        float v0 = sv[rr][colL],     v1 = sv[rr + 1][colL];
        float v8 = sv[rr + 8][colL], v9 = sv[rr + 9][colL];
        float h0 = bf_hi(v0), h1 = bf_hi(v1), h8 = bf_hi(v8), h9 = bf_hi(v9);
        uint4 o;
        o.x = pk_bf2(h0, h1);
        o.y = pk_bf2(h8, h9);
        o.z = pk_bf2(v0 - h0, v1 - h1);
        o.w = pk_bf2(v8 - h8, v9 - h9);
        g_Bf[((long)ks * NB8 + bx * 32 + n8l) * 32 + lane] = o;
    }
}

// ---------------- fused small-ops kernel: 1 block per batch row ----------------
template<bool DUAL, bool TANH>
__device__ __forceinline__ void matop(const float* __restrict__ sA1, const float* __restrict__ sA2,
                                      const float* __restrict__ W1, const float* __restrict__ W2,
                                      const float* __restrict__ bias, float* __restrict__ sOut,
                                      float4 (*sP)[128]) {
    int tid = threadIdx.x;
    int q = tid & 127, s = tid >> 7;
    const float4* w1 = (const float4*)W1;
    const float4* w2 = (const float4*)W2;
    float4 acc = make_float4(0.f, 0.f, 0.f, 0.f);
    int k0 = s * 128;
    #pragma unroll 4
    for (int k = k0; k < k0 + 128; k++) {
        float a1 = sA1[k];
        float4 w = w1[k * 128 + q];
        acc.x = fmaf(a1, w.x, acc.x); acc.y = fmaf(a1, w.y, acc.y);
        acc.z = fmaf(a1, w.z, acc.z); acc.w = fmaf(a1, w.w, acc.w);
        if (DUAL) {
            float a2 = sA2[k];
            float4 v = w2[k * 128 + q];
            acc.x = fmaf(a2, v.x, acc.x); acc.y = fmaf(a2, v.y, acc.y);
            acc.z = fmaf(a2, v.z, acc.z); acc.w = fmaf(a2, v.w, acc.w);
        }
    }
    sP[s][q] = acc;
    __syncthreads();
    if (tid < 128) {
        float4 r0 = sP[0][tid], r1 = sP[1][tid], r2 = sP[2][tid], r3 = sP[3][tid];
        float4 bb = ((const float4*)bias)[tid];
        float o0 = r0.x + r1.x + r2.x + r3.x + bb.x;
        float o1 = r0.y + r1.y + r2.y + r3.y + bb.y;
        float o2 = r0.z + r1.z + r2.z + r3.z + bb.z;
        float o3 = r0.w + r1.w + r2.w + r3.w + bb.w;
        if (TANH) { o0 = tanhf(o0); o1 = tanhf(o1); o2 = tanhf(o2); o3 = tanhf(o3); }
        sOut[tid * 4 + 0] = o0; sOut[tid * 4 + 1] = o1;
        sOut[tid * 4 + 2] = o2; sOut[tid * 4 + 3] = o3;
    }
    __syncthreads();
}

__global__ void __launch_bounds__(512) k_step_small(
    const float* __restrict__ U0, const float* __restrict__ W0, const float* __restrict__ b0,
    const float* __restrict__ V0, const float* __restrict__ c0,
    const float* __restrict__ U1, const float* __restrict__ W1, const float* __restrict__ b1,
    float* __restrict__ out_h, int t, int T) {
    __shared__ float sX[512], sH0[512], sH1[512], sT[512];
    __shared__ float4 sP[4][128];
    __shared__ float sR[512];
    int b = blockIdx.x, tid = threadIdx.x;

    sX[tid]  = g_xcur[b * 512 + tid];
    sH0[tid] = g_h0s[b * 512 + tid];
    sH1[tid] = g_h1s[b * 512 + tid];
    __syncthreads();

    // h0 = tanh(x@U0 + h0p@W0 + b0)
    matop<true, true>(sX, sH0, U0, W0, b0, sT, sP);
    g_h0s[b * 512 + tid] = sT[tid];

    // logits0 = h0@V0 + c0
    matop<false, false>(sT, nullptr, V0, nullptr, c0, sX, sP);

    // x1 = tanh(softmax(logits0))
    {
        float v = sX[tid];
        sR[tid] = v; __syncthreads();
        for (int s = 256; s > 0; s >>= 1) {
            if (tid < s) sR[tid] = fmaxf(sR[tid], sR[tid + s]);
            __syncthreads();
        }
        float M = sR[0]; __syncthreads();
        float e = __expf(v - M);
        sR[tid] = e; __syncthreads();
        for (int s = 256; s > 0; s >>= 1) {
            if (tid < s) sR[tid] += sR[tid + s];
            __syncthreads();
        }
        float S = sR[0]; __syncthreads();
        sX[tid] = tanhf(e / S);
        __syncthreads();
    }

    // h1 = tanh(x1@U1 + h1p@W1 + b1)
    matop<true, true>(sX, sH1, U1, W1, b1, sT, sP);
    g_h1s[b * 512 + tid] = sT[tid];
    out_h[((long)b * T + t) * 512 + tid] = sT[tid];

    // write A-fragments (bf16 hi/lo) for the big GEMM
    {
        int mtile = b >> 4, lr = b & 15;
        int rsel = (lr >> 3) & 1;
        int lanebase = (lr & 7) << 2;
        int ks = tid >> 4, g = tid & 3, hcol = (tid >> 2) & 1, hl = (tid >> 3) & 1;
        int c0i = ks * 16 + hcol * 8 + g * 2;
        float v0 = sT[c0i], v1 = sT[c0i + 1];
        float h0f = bf_hi(v0), h1f = bf_hi(v1);
        uint32_t pk = hl ? pk_bf2(v0 - h0f, v1 - h1f) : pk_bf2(h0f, h1f);
        int reg = (hcol << 1) | rsel;
        int lane = lanebase + g;
        ((uint32_t*)g_Af)[((((hl * 32 + ks) * 2 + mtile) * 32) + lane) * 4 + reg] = pk;
    }
}

// ---------------- big GEMM: 32 x VPAD logits via bf16-split mma + exp epilogue ----------------
__global__ void __launch_bounds__(128, 4) k_big() {
    int tid = threadIdx.x, w = tid >> 5, lane = tid & 31;
    int bx = blockIdx.x;
    int n8base = bx * 16 + w * 4;        // warp covers 32 cols = 4 n8
    float acc[2][4][4];
    #pragma unroll
    for (int m = 0; m < 2; m++)
        #pragma unroll
        for (int n = 0; n < 4; n++)
            #pragma unroll
            for (int r = 0; r < 4; r++) acc[m][n][r] = 0.f;

    #pragma unroll 2
    for (int ks = 0; ks < 32; ks++) {
        uint4 ah0 = g_Af[(ks * 2 + 0) * 32 + lane];
        uint4 ah1 = g_Af[(ks * 2 + 1) * 32 + lane];
        uint4 al0 = g_Af[((32 + ks) * 2 + 0) * 32 + lane];
        uint4 al1 = g_Af[((32 + ks) * 2 + 1) * 32 + lane];
        uint4 bv[4];
        #pragma unroll
        for (int n = 0; n < 4; n++)
            bv[n] = g_Bf[((long)ks * NB8 + n8base + n) * 32 + lane];
        #pragma unroll
        for (int n = 0; n < 4; n++) {
            mma_bf16(acc[0][n], ah0, bv[n].x, bv[n].y);
            mma_bf16(acc[1][n], ah1, bv[n].x, bv[n].y);
            mma_bf16(acc[0][n], al0, bv[n].x, bv[n].y);
            mma_bf16(acc[1][n], al1, bv[n].x, bv[n].y);
            mma_bf16(acc[0][n], ah0, bv[n].z, bv[n].w);
            mma_bf16(acc[1][n], ah1, bv[n].z, bv[n].w);
        }
    }

    // epilogue: bias + exp + per-row partial (sum, max, argmax)
    __shared__ float s_sum[4][32];
    __shared__ float s_max[4][32];
    __shared__ int   s_idx[4][32];
    int colw = bx * 128 + w * 32;
    float rsum[4] = {0.f, 0.f, 0.f, 0.f};
    float rmax[4] = {-3e38f, -3e38f, -3e38f, -3e38f};
    int   ridx[4] = {0, 0, 0, 0};

    #pragma unroll
    for (int m = 0; m < 2; m++) {
        #pragma unroll
        for (int n = 0; n < 4; n++) {
            int c0 = colw + n * 8 + ((lane & 3) << 1);
            float bias0 = g_c1p[c0], bias1 = g_c1p[c0 + 1];
            // regs 0,1: row = m*16 + lane/4
            {
                float l0 = acc[m][n][0] + bias0, l1 = acc[m][n][1] + bias1;
                float e0 = __expf(l0), e1 = __expf(l1);
                int row = m * 16 + (lane >> 2);
                *(float2*)&g_E[(long)row * VPAD + c0] = make_float2(e0, e1);
                int slot = m * 2;
                rsum[slot] += e0 + e1;
                if (l0 > rmax[slot] || (l0 == rmax[slot] && c0 < ridx[slot])) { rmax[slot] = l0; ridx[slot] = c0; }
                if (l1 > rmax[slot] || (l1 == rmax[slot] && c0 + 1 < ridx[slot])) { rmax[slot] = l1; ridx[slot] = c0 + 1; }
            }
            // regs 2,3: row + 8
            {
                float l0 = acc[m][n][2] + bias0, l1 = acc[m][n][3] + bias1;
                float e0 = __expf(l0), e1 = __expf(l1);
                int row = m * 16 + (lane >> 2) + 8;
                *(float2*)&g_E[(long)row * VPAD + c0] = make_float2(e0, e1);
                int slot = m * 2 + 1;
                rsum[slot] += e0 + e1;
                if (l0 > rmax[slot] || (l0 == rmax[slot] && c0 < ridx[slot])) { rmax[slot] = l0; ridx[slot] = c0; }
                if (l1 > rmax[slot] || (l1 == rmax[slot] && c0 + 1 < ridx[slot])) { rmax[slot] = l1; ridx[slot] = c0 + 1; }
            }
        }
    }
    #pragma unroll
    for (int off = 1; off <= 2; off <<= 1) {
        #pragma unroll
        for (int slot = 0; slot < 4; slot++) {
            rsum[slot] += __shfl_xor_sync(0xffffffffu, rsum[slot], off);
            float v = __shfl_xor_sync(0xffffffffu, rmax[slot], off);
            int   i = __shfl_xor_sync(0xffffffffu, ridx[slot], off);
            if (v > rmax[slot] || (v == rmax[slot] && i < ridx[slot])) { rmax[slot] = v; ridx[slot] = i; }
        }
    }
    if ((lane & 3) == 0) {
        #pragma unroll
        for (int slot = 0; slot < 4; slot++) {
            int row = (slot >> 1) * 16 + (lane >> 2) + (slot & 1) * 8;
            s_sum[w][row] = rsum[slot];
            s_max[w][row] = rmax[slot];
            s_idx[w][row] = ridx[slot];
        }
    }
    __syncthreads();
    if (tid < 32) {
        int row = tid;
        float ps = 0.f, pv = -3e38f; int pi = 0;
        #pragma unroll
        for (int ww = 0; ww < 4; ww++) {
            ps += s_sum[ww][row];
            float v = s_max[ww][row]; int i = s_idx[ww][row];
            if (v > pv || (v == pv && i < pi)) { pv = v; pi = i; }
        }
        g_psum[row * NBP + bx] = ps;
        g_pmax[row * NBP + bx] = pv;
        g_pidx[row * NBP + bx] = pi;
    }
}

// ---------------- combine partials + greedy feedback ----------------
__global__ void k_comb(const float* __restrict__ emb) {
    __shared__ float rs[256], rv[256];
    __shared__ int   ri[256];
    int row = blockIdx.x, tid = threadIdx.x;
    float s = 0.f, mv = -3e38f; int mi = 0;
    for (int i = tid; i < NBLK; i += 256) {
        s += g_psum[row * NBP + i];
        float v = g_pmax[row * NBP + i]; int ix = g_pidx[row * NBP + i];
        if (v > mv || (v == mv && ix < mi)) { mv = v; mi = ix; }
    }
    rs[tid] = s; rv[tid] = mv; ri[tid] = mi;
    __syncthreads();
    for (int st = 128; st > 0; st >>= 1) {
        if (tid < st) {
            rs[tid] += rs[tid + st];
            float v = rv[tid + st]; int i = ri[tid + st];
            if (v > rv[tid] || (v == rv[tid] && i < ri[tid])) { rv[tid] = v; ri[tid] = i; }
        }
        __syncthreads();
    }
    if (tid == 0) g_invS[row] = 1.0f / rs[0];
    int am = ri[0];
    for (int j = tid; j < 512; j += 256)
        g_xcur[row * 512 + j] = emb[(long)am * 512 + j];
}

// ---------------- write y ----------------
__global__ void k_writey(float* __restrict__ out_y, int t, int T) {
    int b = blockIdx.y;
    float inv = g_invS[b];
    const float* erow = &g_E[(long)b * VPAD];
    float* yrow = &out_y[((long)b * T + t) * VOCAB];
    for (int j = blockIdx.x * blockDim.x + threadIdx.x; j < VOCAB; j += gridDim.x * blockDim.x)
        yrow[j] = erow[j] * inv;
}

// ---------------- host launcher ----------------
extern "C" void kernel_launch(void* const* d_in, const int* in_sizes, int n_in,
                              void* d_out, int out_size) {
    const int*   x      = (const int*)d_in[0];
    const float* h_prev = (const float*)d_in[3];
    const float* emb    = (const float*)d_in[4];
    const float* U0     = (const float*)d_in[5];
    const float* W0     = (const float*)d_in[6];
    const float* b0     = (const float*)d_in[7];
    const float* V0     = (const float*)d_in[8];
    const float* c0     = (const float*)d_in[9];
    const float* U1     = (const float*)d_in[10];
    const float* W1     = (const float*)d_in[11];
    const float* b1     = (const float*)d_in[12];
    const float* V1     = (const float*)d_in[13];
    const float* c1     = (const float*)d_in[14];

    float* out = (float*)d_out;
    int T = out_size / (BB * (HH + VOCAB));
    float* out_h = out;
    float* out_y = out + (long)BB * T * HH;

    k_init<<<BB, 512>>>(x, h_prev, emb);
    k_pack_c1<<<(VPAD + 255) / 256, 256>>>(c1);
    k_pack_b<<<dim3(197, 32), 256>>>(V1);

    for (int t = 0; t < T; t++) {
        k_step_small<<<BB, 512>>>(U0, W0, b0, V0, c0, U1, W1, b1, out_h, t, T);
        k_big<<<NBLK, 128>>>();
        k_comb<<<BB, 256>>>(emb);
        k_writey<<<dim3(64, BB), 256>>>(out_y, t, T);
    }
}

// round 4
// speedup vs baseline: 4.4189x; 1.9734x over previous
#include <cuda_runtime.h>
#include <cuda_bf16.h>
#include <math.h>
#include <stdint.h>

#define BB 32
#define HH 512
#define VOCAB 50257
#define VPAD  50432          // multiple of 256
#define NB8   (VPAD/8)       // 6304 fragment columns
#define NBLK  (VPAD/256)     // 197 big-gemm blocks (256 cols each)
#define NBP   208            // padded partial stride

// ---------------- device scratch ----------------
__device__ float g_xcur[BB * HH];
__device__ float g_h0s[2][BB * HH];
__device__ float g_h1s[2][BB * HH];
__device__ float g_l0[BB * HH];
__device__ float g_x1[BB * HH];
__device__ uint4 g_Af[2 * 32 * 2 * 32];        // [hl][ks][m][lane] -> A fragments
__device__ uint4 g_Bf[(long)32 * NB8 * 32];    // [ks][n8][lane] -> {bh0,bh1,bl0,bl1} (103MB)
__device__ float g_c1p[VPAD];
__device__ float g_E[BB * VPAD];               // exp(logits)
__device__ float g_psum[BB * NBP];
__device__ float g_pmax[BB * NBP];
__device__ int   g_pidx[BB * NBP];
__device__ float g_invS[BB];

// ---------------- helpers ----------------
__device__ __forceinline__ uint32_t pk_bf2(float a, float b) {
    uint32_t ua = (uint32_t)__bfloat16_as_ushort(__float2bfloat16_rn(a));
    uint32_t ub = (uint32_t)__bfloat16_as_ushort(__float2bfloat16_rn(b));
    return ua | (ub << 16);
}
__device__ __forceinline__ float bf_hi(float v) {
    return __bfloat162float(__float2bfloat16_rn(v));
}
__device__ __forceinline__ void mma_bf16(float* d, const uint4& a, uint32_t b0, uint32_t b1) {
    asm volatile(
        "mma.sync.aligned.m16n8k16.row.col.f32.bf16.bf16.f32 "
        "{%0,%1,%2,%3},{%4,%5,%6,%7},{%8,%9},{%0,%1,%2,%3};\n"
        : "+f"(d[0]), "+f"(d[1]), "+f"(d[2]), "+f"(d[3])
        : "r"(a.x), "r"(a.y), "r"(a.z), "r"(a.w), "r"(b0), "r"(b1));
}

// ---------------- init ----------------
__global__ void k_init(const int* __restrict__ x, const float* __restrict__ h_prev,
                       const float* __restrict__ emb) {
    int b = blockIdx.x, j = threadIdx.x;
    g_xcur[b * HH + j]   = emb[(long)x[b] * HH + j];
    g_h0s[0][b * HH + j] = h_prev[b * HH + j];
    g_h1s[0][b * HH + j] = h_prev[b * HH + j];
}

__global__ void k_pack_c1(const float* __restrict__ c1) {
    int i = blockIdx.x * blockDim.x + threadIdx.x;
    if (i < VPAD) g_c1p[i] = (i < VOCAB) ? c1[i] : -1e30f;
}

// ---------------- pack V1 into bf16-split mma fragment layout ----------------
__global__ void k_pack_b(const float* __restrict__ V1) {
    __shared__ float sv[16][257];
    int bx = blockIdx.x, ks = blockIdx.y, tid = threadIdx.x;
    int cbase = bx * 256;
    #pragma unroll
    for (int r = 0; r < 16; r++) {
        int col = cbase + tid;
        int k = ks * 16 + r;
        sv[r][tid] = (col < VOCAB) ? V1[(long)k * VOCAB + col] : 0.0f;
    }
    __syncthreads();
    for (int e = tid; e < 1024; e += 256) {
        int lane = e & 31, n8l = e >> 5;
        int colL = n8l * 8 + (lane >> 2);
        int rr = (lane & 3) * 2;
        float v0 = sv[rr][colL],     v1 = sv[rr + 1][colL];
        float v8 = sv[rr + 8][colL], v9 = sv[rr + 9][colL];
        float h0 = bf_hi(v0), h1 = bf_hi(v1), h8 = bf_hi(v8), h9 = bf_hi(v9);
        uint4 o;
        o.x = pk_bf2(h0, h1);
        o.y = pk_bf2(h8, h9);
        o.z = pk_bf2(v0 - h0, v1 - h1);
        o.w = pk_bf2(v8 - h8, v9 - h9);
        g_Bf[((long)ks * NB8 + bx * 32 + n8l) * 32 + lane] = o;
    }
}

// ---------------- column-parallel small GEMM ----------------
// out[32,512] = act(A1@W1 (+A2@W2) + bias). grid 128 blocks x 4 cols, 128 threads.
template<bool DUAL, bool TANH>
__global__ void __launch_bounds__(128) k_mat(
        const float* __restrict__ A1, const float* __restrict__ A2,
        const float* __restrict__ W1, const float* __restrict__ W2,
        const float* __restrict__ bias, float* __restrict__ out) {
    __shared__ float sA1[32 * 132];
    __shared__ float sA2[DUAL ? 32 * 132 : 4];
    __shared__ float sW1[4 * 132];
    __shared__ float sW2[DUAL ? 4 * 132 : 4];
    int tid = threadIdx.x;
    int jb = blockIdx.x * 4;
    int jl = tid & 3, r = tid >> 2;
    float acc = 0.f;

    for (int c = 0; c < 4; c++) {
        int k0 = c * 128;
        #pragma unroll
        for (int i = 0; i < 8; i++) {
            int idx = tid + i * 128;
            int rr = idx >> 5, kc = idx & 31;
            *(float4*)(sA1 + rr * 132 + kc * 4) = *(const float4*)(A1 + rr * 512 + k0 + kc * 4);
            if (DUAL)
                *(float4*)(sA2 + rr * 132 + kc * 4) = *(const float4*)(A2 + rr * 512 + k0 + kc * 4);
        }
        #pragma unroll
        for (int i = 0; i < 4; i++) {
            int idx = tid + i * 128;
            int kk = idx >> 2, jj = idx & 3;
            sW1[jj * 132 + kk] = W1[(k0 + kk) * 512 + jb + jj];
            if (DUAL) sW2[jj * 132 + kk] = W2[(k0 + kk) * 512 + jb + jj];
        }
        __syncthreads();
        const float4* a1 = (const float4*)(sA1 + r * 132);
        const float4* w1 = (const float4*)(sW1 + jl * 132);
        const float4* a2 = (const float4*)(sA2 + (DUAL ? r * 132 : 0));
        const float4* w2 = (const float4*)(sW2 + (DUAL ? jl * 132 : 0));
        #pragma unroll
        for (int kc = 0; kc < 32; kc++) {
            float4 av = a1[kc], wv = w1[kc];
            acc = fmaf(av.x, wv.x, fmaf(av.y, wv.y, fmaf(av.z, wv.z, fmaf(av.w, wv.w, acc))));
            if (DUAL) {
                float4 bv = a2[kc], xv = w2[kc];
                acc = fmaf(bv.x, xv.x, fmaf(bv.y, xv.y, fmaf(bv.z, xv.z, fmaf(bv.w, xv.w, acc))));
            }
        }
        __syncthreads();
    }
    float o = acc + bias[jb + jl];
    if (TANH) o = tanhf(o);
    out[r * 512 + jb + jl] = o;
}

// ---------------- layer-1 cell: h1 + out_h + A-fragment writes ----------------
__global__ void __launch_bounds__(128) k_cell1(
        const float* __restrict__ A1, const float* __restrict__ A2,
        const float* __restrict__ W1, const float* __restrict__ W2,
        const float* __restrict__ bias, float* __restrict__ h1out,
        float* __restrict__ out_h, int t, int T) {
    __shared__ float sA1[32 * 132];
    __shared__ float sA2[32 * 132];
    __shared__ float sW1[4 * 132];
    __shared__ float sW2[4 * 132];
    __shared__ float sH[32 * 5];
    int tid = threadIdx.x;
    int jb = blockIdx.x * 4;
    int jl = tid & 3, r = tid >> 2;
    float acc = 0.f;

    for (int c = 0; c < 4; c++) {
        int k0 = c * 128;
        #pragma unroll
        for (int i = 0; i < 8; i++) {
            int idx = tid + i * 128;
            int rr = idx >> 5, kc = idx & 31;
            *(float4*)(sA1 + rr * 132 + kc * 4) = *(const float4*)(A1 + rr * 512 + k0 + kc * 4);
            *(float4*)(sA2 + rr * 132 + kc * 4) = *(const float4*)(A2 + rr * 512 + k0 + kc * 4);
        }
        #pragma unroll
        for (int i = 0; i < 4; i++) {
            int idx = tid + i * 128;
            int kk = idx >> 2, jj = idx & 3;
            sW1[jj * 132 + kk] = W1[(k0 + kk) * 512 + jb + jj];
            sW2[jj * 132 + kk] = W2[(k0 + kk) * 512 + jb + jj];
        }
        __syncthreads();
        const float4* a1 = (const float4*)(sA1 + r * 132);
        const float4* w1 = (const float4*)(sW1 + jl * 132);
        const float4* a2 = (const float4*)(sA2 + r * 132);
        const float4* w2 = (const float4*)(sW2 + jl * 132);
        #pragma unroll
        for (int kc = 0; kc < 32; kc++) {
            float4 av = a1[kc], wv = w1[kc];
            acc = fmaf(av.x, wv.x, fmaf(av.y, wv.y, fmaf(av.z, wv.z, fmaf(av.w, wv.w, acc))));
            float4 bv = a2[kc], xv = w2[kc];
            acc = fmaf(bv.x, xv.x, fmaf(bv.y, xv.y, fmaf(bv.z, xv.z, fmaf(bv.w, xv.w, acc))));
        }
        __syncthreads();
    }
    float o = tanhf(acc + bias[jb + jl]);
    h1out[r * 512 + jb + jl] = o;
    out_h[((long)r * T + t) * 512 + jb + jl] = o;
    sH[r * 5 + jl] = o;
    __syncthreads();

    // write the 128 A-fragment words this block owns (hi + lo planes)
    {
        int hl = tid >> 6, rem = tid & 63;
        int ps = rem & 1, rr = rem >> 1;
        int c0i = jb + ps * 2;
        float v0 = sH[rr * 5 + ps * 2], v1 = sH[rr * 5 + ps * 2 + 1];
        float h0f = bf_hi(v0), h1f = bf_hi(v1);
        uint32_t pk = hl ? pk_bf2(v0 - h0f, v1 - h1f) : pk_bf2(h0f, h1f);
        int ks = c0i >> 4, kk = c0i & 15;
        int hcol = (kk >> 3) & 1, g = (kk >> 1) & 3;
        int lane = (rr & 7) * 4 + g;
        int reg = hcol * 2 + ((rr >> 3) & 1);
        int mtile = rr >> 4;
        ((uint32_t*)g_Af)[(((hl * 32 + ks) * 2 + mtile) * 32 + lane) * 4 + reg] = pk;
    }
}

// ---------------- layer-0 softmax + tanh ----------------
__global__ void k_softmax_tanh(const float* __restrict__ logits, float* __restrict__ x1) {
    int b = blockIdx.x, j = threadIdx.x;
    __shared__ float red[512];
    float l = logits[b * 512 + j];
    red[j] = l; __syncthreads();
    for (int s = 256; s > 0; s >>= 1) {
        if (j < s) red[j] = fmaxf(red[j], red[j + s]);
        __syncthreads();
    }
    float M = red[0]; __syncthreads();
    float e = __expf(l - M);
    red[j] = e; __syncthreads();
    for (int s = 256; s > 0; s >>= 1) {
        if (j < s) red[j] += red[j + s];
        __syncthreads();
    }
    float S = red[0];
    x1[b * 512 + j] = tanhf(e / S);
}

// ---------------- big GEMM: 32 x VPAD via bf16-split mma + exp epilogue ----------------
__global__ void __launch_bounds__(256) k_big() {
    int tid = threadIdx.x, w = tid >> 5, lane = tid & 31;
    int bx = blockIdx.x;
    int n8base = bx * 32 + w * 4;          // warp covers 32 cols = 4 n8
    float acc[2][4][4];
    #pragma unroll
    for (int m = 0; m < 2; m++)
        #pragma unroll
        for (int n = 0; n < 4; n++)
            #pragma unroll
            for (int rr = 0; rr < 4; rr++) acc[m][n][rr] = 0.f;

    #pragma unroll 2
    for (int ks = 0; ks < 32; ks++) {
        uint4 ah0 = g_Af[(ks * 2 + 0) * 32 + lane];
        uint4 ah1 = g_Af[(ks * 2 + 1) * 32 + lane];
        uint4 al0 = g_Af[((32 + ks) * 2 + 0) * 32 + lane];
        uint4 al1 = g_Af[((32 + ks) * 2 + 1) * 32 + lane];
        uint4 bv[4];
        #pragma unroll
        for (int n = 0; n < 4; n++)
            bv[n] = g_Bf[((long)ks * NB8 + n8base + n) * 32 + lane];
        #pragma unroll
        for (int n = 0; n < 4; n++) {
            mma_bf16(acc[0][n], ah0, bv[n].x, bv[n].y);
            mma_bf16(acc[1][n], ah1, bv[n].x, bv[n].y);
            mma_bf16(acc[0][n], al0, bv[n].x, bv[n].y);
            mma_bf16(acc[1][n], al1, bv[n].x, bv[n].y);
            mma_bf16(acc[0][n], ah0, bv[n].z, bv[n].w);
            mma_bf16(acc[1][n], ah1, bv[n].z, bv[n].w);
        }
    }

    __shared__ float s_sum[8][32];
    __shared__ float s_max[8][32];
    __shared__ int   s_idx[8][32];
    int colw = bx * 256 + w * 32;
    float rsum[4] = {0.f, 0.f, 0.f, 0.f};
    float rmax[4] = {-3e38f, -3e38f, -3e38f, -3e38f};
    int   ridx[4] = {0, 0, 0, 0};

    #pragma unroll
    for (int m = 0; m < 2; m++) {
        #pragma unroll
        for (int n = 0; n < 4; n++) {
            int c0 = colw + n * 8 + ((lane & 3) << 1);
            float bias0 = g_c1p[c0], bias1 = g_c1p[c0 + 1];
            {
                float l0 = acc[m][n][0] + bias0, l1 = acc[m][n][1] + bias1;
                float e0 = __expf(l0), e1 = __expf(l1);
                int row = m * 16 + (lane >> 2);
                *(float2*)&g_E[(long)row * VPAD + c0] = make_float2(e0, e1);
                int slot = m * 2;
                rsum[slot] += e0 + e1;
                if (l0 > rmax[slot] || (l0 == rmax[slot] && c0 < ridx[slot])) { rmax[slot] = l0; ridx[slot] = c0; }
                if (l1 > rmax[slot] || (l1 == rmax[slot] && c0 + 1 < ridx[slot])) { rmax[slot] = l1; ridx[slot] = c0 + 1; }
            }
            {
                float l0 = acc[m][n][2] + bias0, l1 = acc[m][n][3] + bias1;
                float e0 = __expf(l0), e1 = __expf(l1);
                int row = m * 16 + (lane >> 2) + 8;
                *(float2*)&g_E[(long)row * VPAD + c0] = make_float2(e0, e1);
                int slot = m * 2 + 1;
                rsum[slot] += e0 + e1;
                if (l0 > rmax[slot] || (l0 == rmax[slot] && c0 < ridx[slot])) { rmax[slot] = l0; ridx[slot] = c0; }
                if (l1 > rmax[slot] || (l1 == rmax[slot] && c0 + 1 < ridx[slot])) { rmax[slot] = l1; ridx[slot] = c0 + 1; }
            }
        }
    }
    #pragma unroll
    for (int off = 1; off <= 2; off <<= 1) {
        #pragma unroll
        for (int slot = 0; slot < 4; slot++) {
            rsum[slot] += __shfl_xor_sync(0xffffffffu, rsum[slot], off);
            float v = __shfl_xor_sync(0xffffffffu, rmax[slot], off);
            int   i = __shfl_xor_sync(0xffffffffu, ridx[slot], off);
            if (v > rmax[slot] || (v == rmax[slot] && i < ridx[slot])) { rmax[slot] = v; ridx[slot] = i; }
        }
    }
    if ((lane & 3) == 0) {
        #pragma unroll
        for (int slot = 0; slot < 4; slot++) {
            int row = (slot >> 1) * 16 + (lane >> 2) + (slot & 1) * 8;
            s_sum[w][row] = rsum[slot];
            s_max[w][row] = rmax[slot];
            s_idx[w][row] = ridx[slot];
        }
    }
    __syncthreads();
    if (tid < 32) {
        int row = tid;
        float ps = 0.f, pv = -3e38f; int pi = 0;
        #pragma unroll
        for (int ww = 0; ww < 8; ww++) {
            ps += s_sum[ww][row];
            float v = s_max[ww][row]; int i = s_idx[ww][row];
            if (v > pv || (v == pv && i < pi)) { pv = v; pi = i; }
        }
        g_psum[row * NBP + bx] = ps;
        g_pmax[row * NBP + bx] = pv;
        g_pidx[row * NBP + bx] = pi;
    }
}

// ---------------- combine partials: invS + argmax + embed feedback ----------------
__global__ void k_comb(const float* __restrict__ emb) {
    __shared__ float rs[128], rv[128];
    __shared__ int   ri[128];
    int row = blockIdx.x, tid = threadIdx.x;
    float s = 0.f, mv = -3e38f; int mi = 0;
    for (int i = tid; i < NBLK; i += 128) {
        s += g_psum[row * NBP + i];
        float v = g_pmax[row * NBP + i]; int ix = g_pidx[row * NBP + i];
        if (v > mv || (v == mv && ix < mi)) { mv = v; mi = ix; }
    }
    rs[tid] = s; rv[tid] = mv; ri[tid] = mi;
    __syncthreads();
    for (int st = 64; st > 0; st >>= 1) {
        if (tid < st) {
            rs[tid] += rs[tid + st];
            float v = rv[tid + st]; int i = ri[tid + st];
            if (v > rv[tid] || (v == rv[tid] && i < ri[tid])) { rv[tid] = v; ri[tid] = i; }
        }
        __syncthreads();
    }
    if (tid == 0) g_invS[row] = 1.0f / rs[0];
    int am = ri[0];
    for (int j = tid; j < 512; j += 128)
        g_xcur[row * 512 + j] = emb[(long)am * 512 + j];
}

// ---------------- write y ----------------
__global__ void k_writey(float* __restrict__ out_y, int t, int T) {
    int b = blockIdx.y;
    float inv = g_invS[b];
    const float* erow = &g_E[(long)b * VPAD];
    float* yrow = &out_y[((long)b * T + t) * VOCAB];
    for (int j = blockIdx.x * blockDim.x + threadIdx.x; j < VOCAB; j += gridDim.x * blockDim.x)
        yrow[j] = erow[j] * inv;
}

// ---------------- host launcher ----------------
extern "C" void kernel_launch(void* const* d_in, const int* in_sizes, int n_in,
                              void* d_out, int out_size) {
    const int*   x      = (const int*)d_in[0];
    const float* h_prev = (const float*)d_in[3];
    const float* emb    = (const float*)d_in[4];
    const float* U0     = (const float*)d_in[5];
    const float* W0     = (const float*)d_in[6];
    const float* b0     = (const float*)d_in[7];
    const float* V0     = (const float*)d_in[8];
    const float* c0     = (const float*)d_in[9];
    const float* U1     = (const float*)d_in[10];
    const float* W1     = (const float*)d_in[11];
    const float* b1     = (const float*)d_in[12];
    const float* V1     = (const float*)d_in[13];
    const float* c1     = (const float*)d_in[14];

    float* out = (float*)d_out;
    int T = out_size / (BB * (HH + VOCAB));
    float* out_h = out;
    float* out_y = out + (long)BB * T * HH;

    float *p_xcur, *p_h0, *p_h1, *p_l0, *p_x1;
    cudaGetSymbolAddress((void**)&p_xcur, g_xcur);
    cudaGetSymbolAddress((void**)&p_h0,   g_h0s);
    cudaGetSymbolAddress((void**)&p_h1,   g_h1s);
    cudaGetSymbolAddress((void**)&p_l0,   g_l0);
    cudaGetSymbolAddress((void**)&p_x1,   g_x1);

    k_init<<<BB, 512>>>(x, h_prev, emb);
    k_pack_c1<<<(VPAD + 255) / 256, 256>>>(c1);
    k_pack_b<<<dim3(197, 32), 256>>>(V1);

    for (int t = 0; t < T; t++) {
        int cur = t & 1;
        float* h0c = p_h0 + cur * BB * HH;
        float* h0n = p_h0 + (cur ^ 1) * BB * HH;
        float* h1c = p_h1 + cur * BB * HH;
        float* h1n = p_h1 + (cur ^ 1) * BB * HH;

        k_mat<true, true><<<128, 128>>>(p_xcur, h0c, U0, W0, b0, h0n);
        k_mat<false, false><<<128, 128>>>(h0n, nullptr, V0, nullptr, c0, p_l0);
        k_softmax_tanh<<<BB, 512>>>(p_l0, p_x1);
        k_cell1<<<128, 128>>>(p_x1, h1c, U1, W1, b1, h1n, out_h, t, T);
        k_big<<<NBLK, 256>>>();
        k_comb<<<BB, 128>>>(emb);
        k_writey<<<dim3(64, BB), 256>>>(out_y, t, T);
    }
}